// round 10
// baseline (speedup 1.0000x reference)
#include <cuda_runtime.h>
#include <cuda_bf16.h>
#include <cuda_fp8.h>
#include <math.h>
#include <stdint.h>

#define BATCH 1024
#define FEAT  2048
#define NCLS  11003
#define NPAD  11008
#define NT1   172           // N tiles of 64 for gemm1
#define NCH   344           // 32-col LSE chunks (NPAD/32)
#define ROWS2 2048          // stacked [v; t]

#define ASCALE 64.0f
#define WSCALE 4.0f

// ---------------- device scratch (static, no runtime alloc) ----------------
__device__ __align__(128) __nv_bfloat16 g_abuf[ROWS2 * FEAT];   // normalized [v;t] bf16 (gemm2)
__device__ __align__(128) uint8_t g_a8[(size_t)ROWS2 * FEAT];   // fp8 v-hat * 64
__device__ __align__(128) uint8_t g_w8t[(size_t)NPAD * FEAT];   // fp8 W^T [n][k] * 4
__device__ float g_colsqp[16 * NPAD];   // per-128k col sq partials (fp32 W)
__device__ float g_ll[ROWS2];           // label logits
__device__ float g_pmax[NCH * ROWS2];   // chunkwise lse partials
__device__ float g_psum[NCH * ROWS2];
__device__ float g_gal_part[256];
__device__ float g_inst_part[32];
__device__ int   g_lab[BATCH];

__device__ __forceinline__ uint8_t to_e4m3(float x) {
    __nv_fp8_e4m3 v(x);
    return *reinterpret_cast<uint8_t*>(&v);
}

// ---------------- prep: normalize rows + labels ----------------
__global__ void normalize_kernel(const float* __restrict__ vis,
                                 const float* __restrict__ txt,
                                 const int* __restrict__ lb) {
    int r = blockIdx.x;                 // 0..2047
    int t = threadIdx.x;                // 256 threads, 8 floats each

    if (r == 0) {
        // labels may be int32 (JAX canonicalization) or true int64; detect via
        // high words of the first 64 ints. lb[2i] read only after int64 confirmed.
        bool is64 = true;
        #pragma unroll
        for (int j = 1; j < 64; j += 2)
            if (lb[j] != 0) is64 = false;
        #pragma unroll
        for (int i = 0; i < 4; i++) {
            int idx = t + 256 * i;
            g_lab[idx] = is64 ? lb[2 * idx] : lb[idx];
        }
    }

    const float* src = (r < BATCH) ? (vis + (size_t)r * FEAT)
                                   : (txt + (size_t)(r - BATCH) * FEAT);
    float4 x0 = ((const float4*)src)[t];
    float4 x1 = ((const float4*)src)[t + 256];
    float ss = x0.x*x0.x + x0.y*x0.y + x0.z*x0.z + x0.w*x0.w
             + x1.x*x1.x + x1.y*x1.y + x1.z*x1.z + x1.w*x1.w;
    #pragma unroll
    for (int o = 16; o > 0; o >>= 1) ss += __shfl_xor_sync(0xffffffffu, ss, o);
    __shared__ float ws[8];
    __shared__ float s_rn;
    if ((t & 31) == 0) ws[t >> 5] = ss;
    __syncthreads();
    if (t == 0) {
        float s = 0.f;
        #pragma unroll
        for (int i = 0; i < 8; i++) s += ws[i];
        s_rn = rsqrtf(s);
    }
    __syncthreads();
    float rn = s_rn;
    __nv_bfloat162* dst = (__nv_bfloat162*)(g_abuf + (size_t)r * FEAT);
    dst[2*t]       = __nv_bfloat162(__float2bfloat16(x0.x*rn), __float2bfloat16(x0.y*rn));
    dst[2*t + 1]   = __nv_bfloat162(__float2bfloat16(x0.z*rn), __float2bfloat16(x0.w*rn));
    dst[512 + 2*t]     = __nv_bfloat162(__float2bfloat16(x1.x*rn), __float2bfloat16(x1.y*rn));
    dst[512 + 2*t + 1] = __nv_bfloat162(__float2bfloat16(x1.z*rn), __float2bfloat16(x1.w*rn));

    float fa = rn * ASCALE;
    uchar4 p0 = make_uchar4(to_e4m3(x0.x*fa), to_e4m3(x0.y*fa),
                            to_e4m3(x0.z*fa), to_e4m3(x0.w*fa));
    uchar4 p1 = make_uchar4(to_e4m3(x1.x*fa), to_e4m3(x1.y*fa),
                            to_e4m3(x1.z*fa), to_e4m3(x1.w*fa));
    uint32_t* d8 = (uint32_t*)(g_a8 + (size_t)r * FEAT);
    d8[t]       = *reinterpret_cast<uint32_t*>(&p0);
    d8[t + 256] = *reinterpret_cast<uint32_t*>(&p1);
}

// ---------------- prep: transpose W -> fp8 [n][k] + colsq partials ----------------
__global__ void wtrans_kernel(const float* __restrict__ W) {
    __shared__ float s[128][33];
    __shared__ float sq[8][33];
    int c0 = blockIdx.x * 32, k0 = blockIdx.y * 128;
    int tx = threadIdx.x, ty = threadIdx.y;
    int c = c0 + tx;
    float p = 0.f;
    #pragma unroll
    for (int i = 0; i < 16; i++) {
        int k = k0 + ty + 8 * i;
        float w = (c < NCLS) ? W[(size_t)k * NCLS + c] : 0.f;
        s[ty + 8 * i][tx] = w;
        p += w * w;
    }
    sq[ty][tx] = p;
    __syncthreads();
    if (ty == 0) {
        float ssum = 0.f;
        #pragma unroll
        for (int i = 0; i < 8; i++) ssum += sq[i][tx];
        g_colsqp[blockIdx.y * NPAD + c] = ssum;
    }
    #pragma unroll
    for (int j = 0; j < 4; j++) {
        int nl = ty + 8 * j;
        int kq = tx;
        uchar4 pk = make_uchar4(to_e4m3(s[4*kq+0][nl] * WSCALE),
                                to_e4m3(s[4*kq+1][nl] * WSCALE),
                                to_e4m3(s[4*kq+2][nl] * WSCALE),
                                to_e4m3(s[4*kq+3][nl] * WSCALE));
        *(uint32_t*)(g_w8t + (size_t)(c0 + nl) * FEAT + k0 + 4 * kq) =
            *reinterpret_cast<uint32_t*>(&pk);
    }
}

// ---------------- mma helpers ----------------
__device__ __forceinline__ void ldmx4(uint32_t* r, uint32_t a) {
    asm volatile("ldmatrix.sync.aligned.m8n8.x4.shared.b16 {%0,%1,%2,%3},[%4];\n"
                 : "=r"(r[0]), "=r"(r[1]), "=r"(r[2]), "=r"(r[3]) : "r"(a));
}
__device__ __forceinline__ void mma16816(float* c, const uint32_t* a, const uint32_t* b) {
    asm volatile("mma.sync.aligned.m16n8k16.row.col.f32.bf16.bf16.f32 "
                 "{%0,%1,%2,%3},{%4,%5,%6,%7},{%8,%9},{%0,%1,%2,%3};\n"
                 : "+f"(c[0]), "+f"(c[1]), "+f"(c[2]), "+f"(c[3])
                 : "r"(a[0]), "r"(a[1]), "r"(a[2]), "r"(a[3]),
                   "r"(b[0]), "r"(b[1]));
}
__device__ __forceinline__ void mma16832f8(float* c, const uint32_t* a, const uint32_t* b) {
    asm volatile("mma.sync.aligned.m16n8k32.row.col.f32.e4m3.e4m3.f32 "
                 "{%0,%1,%2,%3},{%4,%5,%6,%7},{%8,%9},{%0,%1,%2,%3};\n"
                 : "+f"(c[0]), "+f"(c[1]), "+f"(c[2]), "+f"(c[3])
                 : "r"(a[0]), "r"(a[1]), "r"(a[2]), "r"(a[3]),
                   "r"(b[0]), "r"(b[1]));
}
__device__ __forceinline__ void cpa16(uint32_t dst, const void* src) {
    asm volatile("cp.async.cg.shared.global [%0], [%1], 16;" :: "r"(dst), "l"(src));
}
__device__ __forceinline__ void cpa_commit() {
    asm volatile("cp.async.commit_group;" ::: "memory");
}
template <int N> __device__ __forceinline__ void cpa_wait() {
    asm volatile("cp.async.wait_group %0;" :: "n"(N) : "memory");
}

// ======================= GEMM1: fp8 128x64x128B =======================
// 256 threads, 8 warps, warp tile 32x32. XOR-swizzled smem, hoisted addressing,
// 3-stage cp.async pipeline, one __syncthreads per K-stage, 3 CTAs/SM.
// Column inv-norms computed in-prologue from g_colsqp.
#define F8_AB   (128 * 128)             // 16384
#define F8_BB   (64 * 128)              // 8192
#define F8_STG  (F8_AB + F8_BB)         // 24576
#define G1_SMEM (3 * F8_STG)            // 73728
#define G1_NSTG 16                      // FEAT / 128

__global__ __launch_bounds__(256, 3) void gemm1_kernel() {
    extern __shared__ char smem[];
    __shared__ float sInv[64];
    int ntile = blockIdx.x, mtile = blockIdx.y;
    int tid = threadIdx.x, warp = tid >> 5, lane = tid & 31;
    int wm = warp & 3, wn = warp >> 2;

    uint32_t sb = (uint32_t)__cvta_generic_to_shared(smem);
    float c[2][4][4];
    #pragma unroll
    for (int mf = 0; mf < 2; mf++)
        #pragma unroll
        for (int nf = 0; nf < 4; nf++)
            #pragma unroll
            for (int j = 0; j < 4; j++) c[mf][nf][j] = 0.f;

    // ---- hoisted cp.async addressing ----
    int arow = tid >> 3, q = tid & 7;
    uint32_t asw = (uint32_t)((q ^ (arow & 7)) << 4);       // invariant under row+32
    uint32_t adst0 = (uint32_t)(arow * 128) + asw;          // + i*4096
    const uint8_t* asrc0 = g_a8 + ((size_t)(mtile * 128 + arow)) * FEAT + q * 16;
    uint32_t bdst0 = (uint32_t)F8_AB + (uint32_t)(arow * 128) + asw;
    const uint8_t* bsrc0 = g_w8t + ((size_t)(ntile * 64 + arow)) * FEAT + q * 16;

    int koff = 0;
    auto issue_stage = [&](uint32_t bufbase) {
        #pragma unroll
        for (int i = 0; i < 4; i++)
            cpa16(bufbase + adst0 + i * 4096, asrc0 + (size_t)i * 32 * FEAT + koff);
        #pragma unroll
        for (int i = 0; i < 2; i++)
            cpa16(bufbase + bdst0 + i * 4096, bsrc0 + (size_t)i * 32 * FEAT + koff);
        cpa_commit();
        koff += 128;
    };

    // ---- hoisted ldmatrix addressing ----
    int arow0 = wm * 32 + (lane & 15);                       // mf=1: +16 (same &7)
    int brow0 = wn * 32 + (lane & 7) + ((lane >> 4) << 3);   // nh=1: +16 (same &7)
    int ahi = lane >> 4, bhi = (lane >> 3) & 1;
    uint32_t aoff = (uint32_t)(arow0 * 128);
    uint32_t boff = (uint32_t)F8_AB + (uint32_t)(brow0 * 128);
    uint32_t colA[4], colB[4];
    #pragma unroll
    for (int ks = 0; ks < 4; ks++) {
        colA[ks] = (uint32_t)(((ks * 2 + ahi) ^ (arow0 & 7)) << 4);
        colB[ks] = (uint32_t)(((ks * 2 + bhi) ^ (brow0 & 7)) << 4);
    }

    issue_stage(sb);
    issue_stage(sb + F8_STG);

    // fused inv-norm: hidden under pipeline fill
    if (tid < 64) {
        int cidx = ntile * 64 + tid;
        float s = 0.f;
        #pragma unroll
        for (int i = 0; i < 16; i++) s += g_colsqp[i * NPAD + cidx];
        sInv[tid] = (cidx < NCLS) ? (28.0f / (ASCALE * WSCALE)) * rsqrtf(s) : 0.f;
    }

    for (int kt = 0; kt < G1_NSTG; kt++) {
        int buf = kt % 3;
        uint32_t bufbase = sb + buf * F8_STG;
        if (kt < G1_NSTG - 1) cpa_wait<1>(); else cpa_wait<0>();
        __syncthreads();
        if (kt + 2 < G1_NSTG) issue_stage(sb + ((kt + 2) % 3) * F8_STG);

        uint32_t abase = bufbase + aoff;
        uint32_t bbase = bufbase + boff;
        #pragma unroll
        for (int ks = 0; ks < 4; ks++) {         // 4 x k32
            uint32_t a[2][4], b[4][2];
            ldmx4(a[0], abase + colA[ks]);
            ldmx4(a[1], abase + 2048 + colA[ks]);
            {
                uint32_t r[4];
                ldmx4(r, bbase + colB[ks]);
                b[0][0] = r[0]; b[0][1] = r[1];
                b[1][0] = r[2]; b[1][1] = r[3];
                ldmx4(r, bbase + 2048 + colB[ks]);
                b[2][0] = r[0]; b[2][1] = r[1];
                b[3][0] = r[2]; b[3][1] = r[3];
            }
            #pragma unroll
            for (int mf = 0; mf < 2; mf++)
                #pragma unroll
                for (int nf = 0; nf < 4; nf++)
                    mma16832f8(c[mf][nf], a[mf], b[nf]);
        }
    }

    // -------- epilogue: chunkwise logsumexp (32-col chunks) --------
    int g = lane >> 2, tg = lane & 3;
    #pragma unroll
    for (int mf = 0; mf < 2; mf++)
        #pragma unroll
        for (int pr = 0; pr < 2; pr++) {
            int R = mtile * 128 + wm * 32 + mf * 16 + pr * 8 + g;
            int lbl = g_lab[R & (BATCH - 1)];
            float v[8];
            float mx = -1e30f;
            #pragma unroll
            for (int nf = 0; nf < 4; nf++)
                #pragma unroll
                for (int j = 0; j < 2; j++) {
                    int nl = wn * 32 + nf * 8 + tg * 2 + j;
                    int n = ntile * 64 + nl;
                    float val = c[mf][nf][pr * 2 + j] * sInv[nl];
                    if (n >= NCLS) val = -1e30f;
                    if (n == lbl) g_ll[R] = val;
                    v[nf * 2 + j] = val;
                    mx = fmaxf(mx, val);
                }
            mx = fmaxf(mx, __shfl_xor_sync(0xffffffffu, mx, 1));
            mx = fmaxf(mx, __shfl_xor_sync(0xffffffffu, mx, 2));
            float s = 0.f;
            #pragma unroll
            for (int i = 0; i < 8; i++) s += __expf(v[i] - mx);
            s += __shfl_xor_sync(0xffffffffu, s, 1);
            s += __shfl_xor_sync(0xffffffffu, s, 2);
            if (tg == 0) {
                int chunk = ntile * 2 + wn;
                g_pmax[chunk * ROWS2 + R] = mx;
                g_psum[chunk * ROWS2 + R] = s;
            }
        }
}

// ======================= GEMM2: bf16 64x64x64 =======================
// 128 threads, 4 warps, warp tile 32x32: wm = warp&1, wn = warp>>1. 3-stage.
#define B2_ST   72
#define B2_TB   (64 * B2_ST * 2)        // 9216
#define G2_STG  (2 * B2_TB)             // 18432
#define G2_SMEM (3 * G2_STG)            // 55296
#define NSTG2   32

__global__ __launch_bounds__(128, 4) void gemm2_kernel() {
    extern __shared__ char smem[];
    int ntile = blockIdx.x, mtile = blockIdx.y;
    int tid = threadIdx.x, warp = tid >> 5, lane = tid & 31;
    int wm = warp & 1, wn = warp >> 1;
    uint32_t sb = (uint32_t)__cvta_generic_to_shared(smem);

    float c[2][4][4];
    #pragma unroll
    for (int mf = 0; mf < 2; mf++)
        #pragma unroll
        for (int nf = 0; nf < 4; nf++)
            #pragma unroll
            for (int j = 0; j < 4; j++) c[mf][nf][j] = 0.f;

    const __nv_bfloat16* Abase = g_abuf + (size_t)(mtile * 64) * FEAT;
    const __nv_bfloat16* Bbase = g_abuf + (size_t)(BATCH + ntile * 64) * FEAT;

    auto issue_stage = [&](int kt, int buf) {
        uint32_t ab = sb + buf * G2_STG;
        uint32_t bb = ab + B2_TB;
        #pragma unroll
        for (int i = 0; i < 4; i++) {            // A: 64 rows x 64 bf16
            int ch = tid + i * 128;
            int row = ch >> 3, q2 = ch & 7;
            cpa16(ab + row * 144 + q2 * 16,
                  Abase + (size_t)row * FEAT + kt * 64 + q2 * 8);
        }
        #pragma unroll
        for (int i = 0; i < 4; i++) {            // B: 64 rows x 64 bf16
            int ch = tid + i * 128;
            int row = ch >> 3, q2 = ch & 7;
            cpa16(bb + row * 144 + q2 * 16,
                  Bbase + (size_t)row * FEAT + kt * 64 + q2 * 8);
        }
        cpa_commit();
    };

    issue_stage(0, 0);
    issue_stage(1, 1);

    for (int kt = 0; kt < NSTG2; kt++) {
        int buf = kt % 3;
        if (kt < NSTG2 - 1) cpa_wait<1>(); else cpa_wait<0>();
        __syncthreads();
        if (kt + 2 < NSTG2) issue_stage(kt + 2, (kt + 2) % 3);

        uint32_t ab = sb + buf * G2_STG;
        uint32_t bb = ab + B2_TB;
        #pragma unroll
        for (int ks = 0; ks < 4; ks++) {
            uint32_t a[2][4], b[4][2];
            #pragma unroll
            for (int mf = 0; mf < 2; mf++)
                ldmx4(a[mf], ab + ((wm * 32 + mf * 16 + (lane & 15)) * B2_ST +
                                   ks * 16 + ((lane >> 4) << 3)) * 2);
            #pragma unroll
            for (int nh = 0; nh < 2; nh++) {
                uint32_t r[4];
                int nrow = wn * 32 + nh * 16 + (lane & 7) + ((lane >> 4) << 3);
                int kcol = ks * 16 + (((lane >> 3) & 1) << 3);
                ldmx4(r, bb + (nrow * B2_ST + kcol) * 2);
                b[nh * 2][0] = r[0]; b[nh * 2][1] = r[1];
                b[nh * 2 + 1][0] = r[2]; b[nh * 2 + 1][1] = r[3];
            }
            #pragma unroll
            for (int mf = 0; mf < 2; mf++)
                #pragma unroll
                for (int nf = 0; nf < 4; nf++)
                    mma16816(c[mf][nf], a[mf], b[nf]);
        }
    }

    int g = lane >> 2, tg = lane & 3;
    float local = 0.f;
    #pragma unroll
    for (int mf = 0; mf < 2; mf++)
        #pragma unroll
        for (int pr = 0; pr < 2; pr++) {
            int R = mtile * 64 + wm * 32 + mf * 16 + pr * 8 + g;
            int lr = g_lab[R];
            #pragma unroll
            for (int nf = 0; nf < 4; nf++)
                #pragma unroll
                for (int j = 0; j < 2; j++) {
                    int n = ntile * 64 + wn * 32 + nf * 8 + tg * 2 + j;
                    int lc = g_lab[n];
                    float s = c[mf][nf][pr * 2 + j];
                    float x = (lr == lc) ? (-10.f * (s - 0.6f))
                                         : (40.f * (s - 0.4f));
                    local += (x > 15.f) ? x : log1pf(__expf(x));
                }
        }
    #pragma unroll
    for (int o = 16; o > 0; o >>= 1) local += __shfl_xor_sync(0xffffffffu, local, o);
    __shared__ float ws[4];
    if (lane == 0) ws[warp] = local;
    __syncthreads();
    if (tid == 0)
        g_gal_part[blockIdx.y * gridDim.x + blockIdx.x] = ws[0] + ws[1] + ws[2] + ws[3];
}

// ---------------- combine: per-row lse + CE partial (32 blocks x 64) ----------------
__global__ void combine_kernel() {
    int r = blockIdx.x * 64 + threadIdx.x;
    float mx = -1e30f;
    #pragma unroll 8
    for (int i = 0; i < NCH; i++) mx = fmaxf(mx, g_pmax[i * ROWS2 + r]);
    float s = 0.f;
    #pragma unroll 8
    for (int i = 0; i < NCH; i++)
        s += g_psum[i * ROWS2 + r] * __expf(g_pmax[i * ROWS2 + r] - mx);
    float contrib = mx + logf(s) - g_ll[r];

    int lane = threadIdx.x & 31, wid = threadIdx.x >> 5;
    #pragma unroll
    for (int o = 16; o > 0; o >>= 1) contrib += __shfl_xor_sync(0xffffffffu, contrib, o);
    __shared__ float ws[2];
    if (lane == 0) ws[wid] = contrib;
    __syncthreads();
    if (threadIdx.x == 0) g_inst_part[blockIdx.x] = ws[0] + ws[1];
}

__global__ void finalize_kernel(float* __restrict__ out) {
    int t = threadIdx.x;                // 256 threads
    float inst = (t < 32) ? g_inst_part[t] : 0.f;
    float gal = g_gal_part[t];
    #pragma unroll
    for (int o = 16; o > 0; o >>= 1) {
        inst += __shfl_xor_sync(0xffffffffu, inst, o);
        gal  += __shfl_xor_sync(0xffffffffu, gal, o);
    }
    __shared__ float wi[8], wg[8];
    if ((t & 31) == 0) { wi[t >> 5] = inst; wg[t >> 5] = gal; }
    __syncthreads();
    if (t == 0) {
        float si = 0.f, sg = 0.f;
        #pragma unroll
        for (int i = 0; i < 8; i++) { si += wi[i]; sg += wg[i]; }
        out[0] = si * (1.0f / BATCH);
        out[1] = 2.0f * sg / BATCH;
    }
}

// ---------------- launch: fork prep across two streams ----------------
extern "C" void kernel_launch(void* const* d_in, const int* in_sizes, int n_in,
                              void* d_out, int out_size) {
    const float* vis = (const float*)d_in[0];
    const float* txt = (const float*)d_in[1];
    const int* lab = (const int*)d_in[2];
    const float* W = (const float*)d_in[3];
    float* out = (float*)d_out;

    // Lazily created once on the first (non-captured, correctness) call.
    // Work per call is identical; these are host-side handles only.
    static cudaStream_t s2 = nullptr;
    static cudaEvent_t ev_fork = nullptr, ev_join = nullptr;
    if (!s2) {
        cudaStreamCreateWithFlags(&s2, cudaStreamNonBlocking);
        cudaEventCreateWithFlags(&ev_fork, cudaEventDisableTiming);
        cudaEventCreateWithFlags(&ev_join, cudaEventDisableTiming);
        cudaFuncSetAttribute(gemm1_kernel,
                             cudaFuncAttributeMaxDynamicSharedMemorySize, G1_SMEM);
        cudaFuncSetAttribute(gemm2_kernel,
                             cudaFuncAttributeMaxDynamicSharedMemorySize, G2_SMEM);
    }

    // fork: s2 runs normalize -> gemm2 while stream 0 runs wtrans (independent)
    cudaEventRecord(ev_fork, 0);
    cudaStreamWaitEvent(s2, ev_fork, 0);

    normalize_kernel<<<ROWS2, 256, 0, s2>>>(vis, txt, lab);
    gemm2_kernel<<<dim3(16, 16), 128, G2_SMEM, s2>>>();

    wtrans_kernel<<<dim3(NPAD / 32, FEAT / 128), dim3(32, 8)>>>(W);

    // join: gemm1 needs g_a8/g_lab (s2 branch) and g_w8t/g_colsqp (stream 0)
    cudaEventRecord(ev_join, s2);
    cudaStreamWaitEvent(0, ev_join, 0);

    gemm1_kernel<<<dim3(NT1, 16), 256, G1_SMEM>>>();   // 4th kernel -> ncu target
    combine_kernel<<<32, 64>>>();
    finalize_kernel<<<1, 256>>>(out);
}

// round 11
// speedup vs baseline: 1.0998x; 1.0998x over previous
#include <cuda_runtime.h>
#include <cuda_bf16.h>
#include <cuda_fp8.h>
#include <math.h>
#include <stdint.h>

#define BATCH 1024
#define FEAT  2048
#define NCLS  11003
#define NPAD  11008
#define NT1   172           // N tiles of 64 for gemm1
#define NCH   344           // 32-col LSE chunks (NPAD/32)
#define ROWS2 2048          // stacked [v; t]

#define ASCALE 64.0f
#define WSCALE 4.0f

#define WT_BLOCKS (344 * 16)            // wtrans sub-grid
#define G1_BLOCKS (NT1 * 16)            // 2752
#define G2_BLOCKS 256                   // gemm2 64x64 tiles (16 m x 16 n)

// ---------------- device scratch (static, no runtime alloc) ----------------
__device__ __align__(128) __nv_bfloat16 g_abuf[ROWS2 * FEAT];   // normalized [v;t] bf16
__device__ __align__(128) uint8_t g_a8[(size_t)ROWS2 * FEAT];   // fp8 v-hat * 64
__device__ __align__(128) uint8_t g_w8t[(size_t)NPAD * FEAT];   // fp8 W^T [n][k] * 4
__device__ float g_colsqp[16 * NPAD];
__device__ float g_ll[ROWS2];
__device__ float g_pmax[NCH * ROWS2];
__device__ float g_psum[NCH * ROWS2];
__device__ float g_gal_part[G2_BLOCKS];
__device__ float g_inst_part[32];
__device__ int   g_lab[BATCH];
__device__ int   g_ctr;                 // zero-initialized; self-resetting ticket

__device__ __forceinline__ uint8_t to_e4m3(float x) {
    __nv_fp8_e4m3 v(x);
    return *reinterpret_cast<uint8_t*>(&v);
}

// ======================= prep_fused: wtrans + normalize =======================
__global__ void prep_fused_kernel(const float* __restrict__ W,
                                  const float* __restrict__ vis,
                                  const float* __restrict__ txt,
                                  const int* __restrict__ lb) {
    __shared__ float s[128][33];
    __shared__ float sq[8][33];
    int bid = blockIdx.x;
    int t = threadIdx.x;

    if (bid < WT_BLOCKS) {
        // ---- wtrans: W -> fp8 [n][k] + colsq partials ----
        int tx = t & 31, ty = t >> 5;
        int c0 = (bid % 344) * 32, k0 = (bid / 344) * 128;
        int c = c0 + tx;
        float p = 0.f;
        #pragma unroll
        for (int i = 0; i < 16; i++) {
            int k = k0 + ty + 8 * i;
            float w = (c < NCLS) ? W[(size_t)k * NCLS + c] : 0.f;
            s[ty + 8 * i][tx] = w;
            p += w * w;
        }
        sq[ty][tx] = p;
        __syncthreads();
        if (ty == 0) {
            float ssum = 0.f;
            #pragma unroll
            for (int i = 0; i < 8; i++) ssum += sq[i][tx];
            g_colsqp[(bid / 344) * NPAD + c] = ssum;
        }
        #pragma unroll
        for (int j = 0; j < 4; j++) {
            int nl = ty + 8 * j;
            int kq = tx;
            uchar4 pk = make_uchar4(to_e4m3(s[4*kq+0][nl] * WSCALE),
                                    to_e4m3(s[4*kq+1][nl] * WSCALE),
                                    to_e4m3(s[4*kq+2][nl] * WSCALE),
                                    to_e4m3(s[4*kq+3][nl] * WSCALE));
            *(uint32_t*)(g_w8t + (size_t)(c0 + nl) * FEAT + k0 + 4 * kq) =
                *reinterpret_cast<uint32_t*>(&pk);
        }
    } else {
        // ---- normalize row r + labels (block WT_BLOCKS handles labels) ----
        int r = bid - WT_BLOCKS;        // 0..2047
        if (r == 0) {
            bool is64 = true;
            #pragma unroll
            for (int j = 1; j < 64; j += 2)
                if (lb[j] != 0) is64 = false;
            #pragma unroll
            for (int i = 0; i < 4; i++) {
                int idx = t + 256 * i;
                g_lab[idx] = is64 ? lb[2 * idx] : lb[idx];
            }
        }
        const float* src = (r < BATCH) ? (vis + (size_t)r * FEAT)
                                       : (txt + (size_t)(r - BATCH) * FEAT);
        float4 x0 = ((const float4*)src)[t];
        float4 x1 = ((const float4*)src)[t + 256];
        float ss = x0.x*x0.x + x0.y*x0.y + x0.z*x0.z + x0.w*x0.w
                 + x1.x*x1.x + x1.y*x1.y + x1.z*x1.z + x1.w*x1.w;
        #pragma unroll
        for (int o = 16; o > 0; o >>= 1) ss += __shfl_xor_sync(0xffffffffu, ss, o);
        float* ws = &sq[0][0];
        if ((t & 31) == 0) ws[t >> 5] = ss;
        __syncthreads();
        if (t == 0) {
            float sum = 0.f;
            #pragma unroll
            for (int i = 0; i < 8; i++) sum += ws[i];
            ws[8] = rsqrtf(sum);
        }
        __syncthreads();
        float rn = ws[8];
        __nv_bfloat162* dst = (__nv_bfloat162*)(g_abuf + (size_t)r * FEAT);
        dst[2*t]       = __nv_bfloat162(__float2bfloat16(x0.x*rn), __float2bfloat16(x0.y*rn));
        dst[2*t + 1]   = __nv_bfloat162(__float2bfloat16(x0.z*rn), __float2bfloat16(x0.w*rn));
        dst[512 + 2*t]     = __nv_bfloat162(__float2bfloat16(x1.x*rn), __float2bfloat16(x1.y*rn));
        dst[512 + 2*t + 1] = __nv_bfloat162(__float2bfloat16(x1.z*rn), __float2bfloat16(x1.w*rn));

        float fa = rn * ASCALE;
        uchar4 p0 = make_uchar4(to_e4m3(x0.x*fa), to_e4m3(x0.y*fa),
                                to_e4m3(x0.z*fa), to_e4m3(x0.w*fa));
        uchar4 p1 = make_uchar4(to_e4m3(x1.x*fa), to_e4m3(x1.y*fa),
                                to_e4m3(x1.z*fa), to_e4m3(x1.w*fa));
        uint32_t* d8 = (uint32_t*)(g_a8 + (size_t)r * FEAT);
        d8[t]       = *reinterpret_cast<uint32_t*>(&p0);
        d8[t + 256] = *reinterpret_cast<uint32_t*>(&p1);
    }
}

// ---------------- mma helpers ----------------
__device__ __forceinline__ void ldmx4(uint32_t* r, uint32_t a) {
    asm volatile("ldmatrix.sync.aligned.m8n8.x4.shared.b16 {%0,%1,%2,%3},[%4];\n"
                 : "=r"(r[0]), "=r"(r[1]), "=r"(r[2]), "=r"(r[3]) : "r"(a));
}
__device__ __forceinline__ void mma16816(float* c, const uint32_t* a, const uint32_t* b) {
    asm volatile("mma.sync.aligned.m16n8k16.row.col.f32.bf16.bf16.f32 "
                 "{%0,%1,%2,%3},{%4,%5,%6,%7},{%8,%9},{%0,%1,%2,%3};\n"
                 : "+f"(c[0]), "+f"(c[1]), "+f"(c[2]), "+f"(c[3])
                 : "r"(a[0]), "r"(a[1]), "r"(a[2]), "r"(a[3]),
                   "r"(b[0]), "r"(b[1]));
}
__device__ __forceinline__ void mma16832f8(float* c, const uint32_t* a, const uint32_t* b) {
    asm volatile("mma.sync.aligned.m16n8k32.row.col.f32.e4m3.e4m3.f32 "
                 "{%0,%1,%2,%3},{%4,%5,%6,%7},{%8,%9},{%0,%1,%2,%3};\n"
                 : "+f"(c[0]), "+f"(c[1]), "+f"(c[2]), "+f"(c[3])
                 : "r"(a[0]), "r"(a[1]), "r"(a[2]), "r"(a[3]),
                   "r"(b[0]), "r"(b[1]));
}
__device__ __forceinline__ void cpa16(uint32_t dst, const void* src) {
    asm volatile("cp.async.cg.shared.global [%0], [%1], 16;" :: "r"(dst), "l"(src));
}
__device__ __forceinline__ void cpa_commit() {
    asm volatile("cp.async.commit_group;" ::: "memory");
}
template <int N> __device__ __forceinline__ void cpa_wait() {
    asm volatile("cp.async.wait_group %0;" :: "n"(N) : "memory");
}

// ======================= gemm_fused =======================
// blocks [0, G1_BLOCKS): gemm1 fp8 128x64x128B (unchanged R9 core)
// blocks [G1_BLOCKS, +G2_BLOCKS): gemm2 bf16 64x64 (k-chunk = 64 bf16 = 128B,
//   byte-identical smem layout & swizzle; 512-mma per-warp chain matches gemm1
//   CTA duration, so these fill gemm1's 80%-empty last wave)
#define F8_AB   (128 * 128)             // 16384
#define F8_BB   (64 * 128)              // 8192
#define F8_STG  (F8_AB + F8_BB)         // 24576
#define G1_SMEM (3 * F8_STG)            // 73728
#define G1_NSTG 16
#define G2_NSTG 32

__global__ __launch_bounds__(256, 3) void gemm_fused_kernel() {
    extern __shared__ char smem[];
    __shared__ float sInv[64];
    int tid = threadIdx.x, warp = tid >> 5, lane = tid & 31;
    uint32_t sb = (uint32_t)__cvta_generic_to_shared(smem);
    int arow = tid >> 3, q = tid & 7;
    uint32_t asw = (uint32_t)((q ^ (arow & 7)) << 4);

    if (blockIdx.x < G1_BLOCKS) {
        // ================= gemm1: fp8 logits + LSE =================
        int ntile = blockIdx.x % NT1, mtile = blockIdx.x / NT1;
        int wm = warp & 3, wn = warp >> 2;
        float c[2][4][4];
        #pragma unroll
        for (int mf = 0; mf < 2; mf++)
            #pragma unroll
            for (int nf = 0; nf < 4; nf++)
                #pragma unroll
                for (int j = 0; j < 4; j++) c[mf][nf][j] = 0.f;

        uint32_t adst0 = (uint32_t)(arow * 128) + asw;
        const uint8_t* asrc0 = g_a8 + ((size_t)(mtile * 128 + arow)) * FEAT + q * 16;
        uint32_t bdst0 = (uint32_t)F8_AB + (uint32_t)(arow * 128) + asw;
        const uint8_t* bsrc0 = g_w8t + ((size_t)(ntile * 64 + arow)) * FEAT + q * 16;

        int koff = 0;
        auto issue_stage = [&](uint32_t bufbase) {
            #pragma unroll
            for (int i = 0; i < 4; i++)
                cpa16(bufbase + adst0 + i * 4096, asrc0 + (size_t)i * 32 * FEAT + koff);
            #pragma unroll
            for (int i = 0; i < 2; i++)
                cpa16(bufbase + bdst0 + i * 4096, bsrc0 + (size_t)i * 32 * FEAT + koff);
            cpa_commit();
            koff += 128;
        };

        int arow0 = wm * 32 + (lane & 15);
        int brow0 = wn * 32 + (lane & 7) + ((lane >> 4) << 3);
        int ahi = lane >> 4, bhi = (lane >> 3) & 1;
        uint32_t aoff = (uint32_t)(arow0 * 128);
        uint32_t boff = (uint32_t)F8_AB + (uint32_t)(brow0 * 128);
        uint32_t colA[4], colB[4];
        #pragma unroll
        for (int ks = 0; ks < 4; ks++) {
            colA[ks] = (uint32_t)(((ks * 2 + ahi) ^ (arow0 & 7)) << 4);
            colB[ks] = (uint32_t)(((ks * 2 + bhi) ^ (brow0 & 7)) << 4);
        }

        issue_stage(sb);
        issue_stage(sb + F8_STG);

        if (tid < 64) {
            int cidx = ntile * 64 + tid;
            float s = 0.f;
            #pragma unroll
            for (int i = 0; i < 16; i++) s += g_colsqp[i * NPAD + cidx];
            sInv[tid] = (cidx < NCLS) ? (28.0f / (ASCALE * WSCALE)) * rsqrtf(s) : 0.f;
        }

        for (int kt = 0; kt < G1_NSTG; kt++) {
            uint32_t bufbase = sb + (kt % 3) * F8_STG;
            if (kt < G1_NSTG - 1) cpa_wait<1>(); else cpa_wait<0>();
            __syncthreads();
            if (kt + 2 < G1_NSTG) issue_stage(sb + ((kt + 2) % 3) * F8_STG);

            uint32_t abase = bufbase + aoff;
            uint32_t bbase = bufbase + boff;
            #pragma unroll
            for (int ks = 0; ks < 4; ks++) {
                uint32_t a[2][4], b[4][2];
                ldmx4(a[0], abase + colA[ks]);
                ldmx4(a[1], abase + 2048 + colA[ks]);
                {
                    uint32_t r[4];
                    ldmx4(r, bbase + colB[ks]);
                    b[0][0] = r[0]; b[0][1] = r[1];
                    b[1][0] = r[2]; b[1][1] = r[3];
                    ldmx4(r, bbase + 2048 + colB[ks]);
                    b[2][0] = r[0]; b[2][1] = r[1];
                    b[3][0] = r[2]; b[3][1] = r[3];
                }
                #pragma unroll
                for (int mf = 0; mf < 2; mf++)
                    #pragma unroll
                    for (int nf = 0; nf < 4; nf++)
                        mma16832f8(c[mf][nf], a[mf], b[nf]);
            }
        }

        int g = lane >> 2, tg = lane & 3;
        #pragma unroll
        for (int mf = 0; mf < 2; mf++)
            #pragma unroll
            for (int pr = 0; pr < 2; pr++) {
                int R = mtile * 128 + wm * 32 + mf * 16 + pr * 8 + g;
                int lbl = g_lab[R & (BATCH - 1)];
                float v[8];
                float mx = -1e30f;
                #pragma unroll
                for (int nf = 0; nf < 4; nf++)
                    #pragma unroll
                    for (int j = 0; j < 2; j++) {
                        int nl = wn * 32 + nf * 8 + tg * 2 + j;
                        int n = ntile * 64 + nl;
                        float val = c[mf][nf][pr * 2 + j] * sInv[nl];
                        if (n >= NCLS) val = -1e30f;
                        if (n == lbl) g_ll[R] = val;
                        v[nf * 2 + j] = val;
                        mx = fmaxf(mx, val);
                    }
                mx = fmaxf(mx, __shfl_xor_sync(0xffffffffu, mx, 1));
                mx = fmaxf(mx, __shfl_xor_sync(0xffffffffu, mx, 2));
                float s = 0.f;
                #pragma unroll
                for (int i = 0; i < 8; i++) s += __expf(v[i] - mx);
                s += __shfl_xor_sync(0xffffffffu, s, 1);
                s += __shfl_xor_sync(0xffffffffu, s, 2);
                if (tg == 0) {
                    int chunk = ntile * 2 + wn;
                    g_pmax[chunk * ROWS2 + R] = mx;
                    g_psum[chunk * ROWS2 + R] = s;
                }
            }
    } else {
        // ================= gemm2: bf16 sim + soft-margin =================
        int bid2 = blockIdx.x - G1_BLOCKS;
        int ntile2 = bid2 & 15, mtile2 = bid2 >> 4;   // 16 x 16
        int wm = warp & 1, wn = warp >> 1;            // 2 x 4 warps: 32-row x 16-col
        float c[2][2][4];
        #pragma unroll
        for (int mf = 0; mf < 2; mf++)
            #pragma unroll
            for (int nf = 0; nf < 2; nf++)
                #pragma unroll
                for (int j = 0; j < 4; j++) c[mf][nf][j] = 0.f;

        const uint8_t* ab8 = (const uint8_t*)g_abuf;
        uint32_t adst0 = (uint32_t)(arow * 128) + asw;
        const uint8_t* asrc0 = ab8 + ((size_t)(mtile2 * 64 + arow)) * (FEAT * 2) + q * 16;
        uint32_t bdst0 = (uint32_t)F8_BB + (uint32_t)(arow * 128) + asw;  // B at +8192
        const uint8_t* bsrc0 = ab8 + ((size_t)(BATCH + ntile2 * 64 + arow)) * (FEAT * 2) + q * 16;

        int koff = 0;
        auto issue_stage2 = [&](uint32_t bufbase) {
            #pragma unroll
            for (int i = 0; i < 2; i++)
                cpa16(bufbase + adst0 + i * 4096, asrc0 + (size_t)i * 32 * (FEAT * 2) + koff);
            #pragma unroll
            for (int i = 0; i < 2; i++)
                cpa16(bufbase + bdst0 + i * 4096, bsrc0 + (size_t)i * 32 * (FEAT * 2) + koff);
            cpa_commit();
            koff += 128;
        };

        int arow0 = wm * 32 + (lane & 15);
        int brow0 = wn * 16 + (lane & 7) + ((lane >> 4) << 3);
        int ahi = lane >> 4, bhi = (lane >> 3) & 1;
        uint32_t aoff = (uint32_t)(arow0 * 128);
        uint32_t boff = (uint32_t)F8_BB + (uint32_t)(brow0 * 128);
        uint32_t colA[4], colB[4];
        #pragma unroll
        for (int ks = 0; ks < 4; ks++) {
            colA[ks] = (uint32_t)(((ks * 2 + ahi) ^ (arow0 & 7)) << 4);
            colB[ks] = (uint32_t)(((ks * 2 + bhi) ^ (brow0 & 7)) << 4);
        }

        issue_stage2(sb);
        issue_stage2(sb + F8_STG);

        for (int kt = 0; kt < G2_NSTG; kt++) {
            uint32_t bufbase = sb + (kt % 3) * F8_STG;
            if (kt < G2_NSTG - 1) cpa_wait<1>(); else cpa_wait<0>();
            __syncthreads();
            if (kt + 2 < G2_NSTG) issue_stage2(sb + ((kt + 2) % 3) * F8_STG);

            uint32_t abase = bufbase + aoff;
            uint32_t bbase = bufbase + boff;
            #pragma unroll
            for (int ks = 0; ks < 4; ks++) {
                uint32_t a[2][4], b[2][2];
                ldmx4(a[0], abase + colA[ks]);
                ldmx4(a[1], abase + 2048 + colA[ks]);
                {
                    uint32_t r[4];
                    ldmx4(r, bbase + colB[ks]);
                    b[0][0] = r[0]; b[0][1] = r[1];
                    b[1][0] = r[2]; b[1][1] = r[3];
                }
                #pragma unroll
                for (int mf = 0; mf < 2; mf++)
                    #pragma unroll
                    for (int nf = 0; nf < 2; nf++)
                        mma16816(c[mf][nf], a[mf], b[nf]);
            }
        }

        int g = lane >> 2, tg = lane & 3;
        float local = 0.f;
        #pragma unroll
        for (int mf = 0; mf < 2; mf++)
            #pragma unroll
            for (int pr = 0; pr < 2; pr++) {
                int R = mtile2 * 64 + wm * 32 + mf * 16 + pr * 8 + g;
                int lr = g_lab[R];
                #pragma unroll
                for (int nf = 0; nf < 2; nf++)
                    #pragma unroll
                    for (int j = 0; j < 2; j++) {
                        int n = ntile2 * 64 + wn * 16 + nf * 8 + tg * 2 + j;
                        int lc = g_lab[n];
                        float s = c[mf][nf][pr * 2 + j];
                        float x = (lr == lc) ? (-10.f * (s - 0.6f))
                                             : (40.f * (s - 0.4f));
                        local += (x > 15.f) ? x : log1pf(__expf(x));
                    }
            }
        #pragma unroll
        for (int o = 16; o > 0; o >>= 1) local += __shfl_xor_sync(0xffffffffu, local, o);
        if (lane == 0) sInv[warp] = local;      // reuse sInv as scratch
        __syncthreads();
        if (tid == 0) {
            float t2 = 0.f;
            #pragma unroll
            for (int i = 0; i < 8; i++) t2 += sInv[i];
            g_gal_part[bid2] = t2;
        }
    }
}

// ---------------- combine + finalize (last-block pattern) ----------------
__global__ void combine_final_kernel(float* __restrict__ out) {
    int r = blockIdx.x * 64 + threadIdx.x;
    float mx = -1e30f;
    #pragma unroll 8
    for (int i = 0; i < NCH; i++) mx = fmaxf(mx, g_pmax[i * ROWS2 + r]);
    float s = 0.f;
    #pragma unroll 8
    for (int i = 0; i < NCH; i++)
        s += g_psum[i * ROWS2 + r] * __expf(g_pmax[i * ROWS2 + r] - mx);
    float contrib = mx + logf(s) - g_ll[r];

    int lane = threadIdx.x & 31, wid = threadIdx.x >> 5;
    #pragma unroll
    for (int o = 16; o > 0; o >>= 1) contrib += __shfl_xor_sync(0xffffffffu, contrib, o);
    __shared__ float ws[2];
    __shared__ int s_ticket;
    if (lane == 0) ws[wid] = contrib;
    __syncthreads();
    if (threadIdx.x == 0) {
        g_inst_part[blockIdx.x] = ws[0] + ws[1];
        __threadfence();
        s_ticket = atomicAdd(&g_ctr, 1);
    }
    __syncthreads();
    if (s_ticket == 31) {
        // last block: all 32 g_inst_part entries visible; fixed-order sums
        if (threadIdx.x == 0) {
            float si = 0.f;
            for (int i = 0; i < 32; i++) si += g_inst_part[i];
            float sg = 0.f;
            for (int i = 0; i < G2_BLOCKS; i++) sg += g_gal_part[i];
            out[0] = si * (1.0f / BATCH);
            out[1] = 2.0f * sg / BATCH;
            g_ctr = 0;                   // reset for next graph replay
        }
    }
}

// ---------------- launch: 3 kernels, one stream ----------------
extern "C" void kernel_launch(void* const* d_in, const int* in_sizes, int n_in,
                              void* d_out, int out_size) {
    const float* vis = (const float*)d_in[0];
    const float* txt = (const float*)d_in[1];
    const int* lab = (const int*)d_in[2];
    const float* W = (const float*)d_in[3];
    float* out = (float*)d_out;

    cudaFuncSetAttribute(gemm_fused_kernel,
                         cudaFuncAttributeMaxDynamicSharedMemorySize, G1_SMEM);

    prep_fused_kernel<<<WT_BLOCKS + ROWS2, 256>>>(W, vis, txt, lab);
    gemm_fused_kernel<<<G1_BLOCKS + G2_BLOCKS, 256, G1_SMEM>>>();
    combine_final_kernel<<<32, 64>>>(out);
}